// round 8
// baseline (speedup 1.0000x reference)
#include <cuda_runtime.h>
#include <cstddef>

// PathSampling:
//  paths      [n_node, 32, 8] int32
//  edge_ids   [n_node, 32, 7] int32
//  rand_lens  [n_node, 32]    int32
//  centrality [n_graph]       float32
//  k_path = 8
//
// masked_paths[n,p,j] = (j > rand_lens[n,p]) ? -1 : paths[n,p,j]
// score[n,p] = sum_j centrality[masked_paths[n,p,j]] (masked -> +0, exact)
// top-8 paths per node by score (ties: lower path index, per lax.top_k)
// out (float32): concat(paths_sel [n,8,8], edge_ids_sel [n,8,7]); values
// int->float (exact: ids < 2^24; mask -> -1.0f).
//
// R8: 2 nodes per warp, all loads (lens/paths/gathers for BOTH nodes) issued
// before any consumption -> ~2x per-warp MLP to hide gather latency.
// Selection = R6's rank loop + ballot pack (proven faster than bitonic).

#define N_PATH 32
#define L_PATH 8
#define K_SEL  8
#define E_PER  (L_PATH - 1)           // 7
#define E_TOT  (K_SEL * E_PER)        // 56

__global__ void path_sampling_kernel(
    const int*   __restrict__ paths,
    const int*   __restrict__ edge_ids,
    const int*   __restrict__ rand_lens,
    const float* __restrict__ centrality,
    float*       __restrict__ out_paths,   // [n_node, 8, 8] float32
    float*       __restrict__ out_edges,   // [n_node, 8, 7] float32 or nullptr
    int n_node)
{
    const int warp_id = (blockIdx.x * blockDim.x + threadIdx.x) >> 5;
    const int lane    = threadIdx.x & 31;
    const int node0   = warp_id * 2;
    if (node0 >= n_node) return;
    const bool have1  = (node0 + 1) < n_node;   // warp-uniform

    // ---------- front-batched loads for BOTH nodes ----------
    int rl[2];
    int pj[2][L_PATH];
    float c[2][L_PATH];

    rl[0] = __ldcs(rand_lens + (size_t)node0 * N_PATH + lane);
    rl[1] = have1 ? __ldcs(rand_lens + (size_t)(node0 + 1) * N_PATH + lane) : 0;

#pragma unroll
    for (int u = 0; u < 2; u++) {
        if (u == 1 && !have1) break;
        const int4* p4 = reinterpret_cast<const int4*>(
            paths + (size_t)(node0 + u) * N_PATH * L_PATH);
        int4 a = __ldcs(p4 + lane * 2);
        int4 b = __ldcs(p4 + lane * 2 + 1);
        pj[u][0] = a.x; pj[u][1] = a.y; pj[u][2] = a.z; pj[u][3] = a.w;
        pj[u][4] = b.x; pj[u][5] = b.y; pj[u][6] = b.z; pj[u][7] = b.w;
    }

    // Predicated centrality gathers for both nodes, all issued before the
    // first sum (masked adds are exactly +0.0f, matching the zero-padded
    // reference gather).
#pragma unroll
    for (int u = 0; u < 2; u++) {
        if (u == 1 && !have1) break;
#pragma unroll
        for (int j = 0; j < L_PATH; j++) {
            c[u][j] = (j <= rl[u]) ? __ldg(centrality + pj[u][j]) : 0.0f;
        }
    }

    // ---------- per-node: sum, mask, rank, output ----------
#pragma unroll
    for (int u = 0; u < 2; u++) {
        if (u == 1 && !have1) break;
        const int node = node0 + u;

        float s = 0.0f;
#pragma unroll
        for (int j = 0; j < L_PATH; j++) s += c[u][j];   // matches jnp.sum order

#pragma unroll
        for (int j = 0; j < L_PATH; j++) {
            if (j > rl[u]) pj[u][j] = -1;
        }

        // Stable rank: #{k : s_k > s OR (s_k == s AND k < lane)} — lax.top_k
        // tie-break; ranks are a permutation of 0..31.
        int rank = 0;
#pragma unroll
        for (int k = 0; k < 32; k++) {
            float sk = __shfl_sync(0xffffffffu, s, k);
            rank += (sk > s) || (sk == s && k < lane);
        }

        // rank -> lane map for the 8 winners, 5 bits each in a uint64
        unsigned long long src_packed = 0ull;
#pragma unroll
        for (int r = 0; r < K_SEL; r++) {
            unsigned bal = __ballot_sync(0xffffffffu, rank == r);
            src_packed |= (unsigned long long)(__ffs(bal) - 1) << (5 * r);
        }

        // Winner lanes write their own masked path row (2 x STG.128.CS;
        // the 8 winners cover a contiguous 256B block).
        if (rank < K_SEL) {
            float4* op = reinterpret_cast<float4*>(
                out_paths + ((size_t)node * K_SEL + rank) * L_PATH);
            __stcs(op,     make_float4((float)pj[u][0], (float)pj[u][1],
                                       (float)pj[u][2], (float)pj[u][3]));
            __stcs(op + 1, make_float4((float)pj[u][4], (float)pj[u][5],
                                       (float)pj[u][6], (float)pj[u][7]));
        }

        // Cooperative edge copy: 32 lanes move the 56 selected edge ints.
        // Sources in one contiguous 896B block; destination 224B contiguous.
        if (out_edges != nullptr) {
            const int* eb = edge_ids + (size_t)node * N_PATH * E_PER;
            float*     ew = out_edges + (size_t)node * E_TOT;
#pragma unroll
            for (int t = lane; t < E_TOT; t += 32) {
                int w = t / E_PER;
                int j = t - w * E_PER;
                int srcl = (int)((src_packed >> (5 * w)) & 31ull);
                __stcs(ew + t, (float)__ldcs(eb + srcl * E_PER + j));
            }
        }
    }
}

extern "C" void kernel_launch(void* const* d_in, const int* in_sizes, int n_in,
                              void* d_out, int out_size)
{
    // ---- bind inputs by size (immune to metadata ordering) ----
    const void* ptr[8];
    long long   sz[8];
    int m = n_in > 8 ? 8 : n_in;
    for (int i = 0; i < m; i++) { ptr[i] = d_in[i]; sz[i] = in_sizes[i]; }

    int i_paths = 0;
    for (int i = 1; i < m; i++) if (sz[i] > sz[i_paths]) i_paths = i;
    int i_edges = -1;
    for (int i = 0; i < m; i++) {
        if (i == i_paths) continue;
        if (i_edges < 0 || sz[i] > sz[i_edges]) i_edges = i;
    }

    const long long oo = (long long)out_size;
    const long long np_sz = sz[i_paths];
    long long n_node_ll;
    bool has_edges;
    if (oo % (K_SEL * (2 * L_PATH - 1)) == 0 && np_sz == (oo / 120) * 256) {
        n_node_ll = oo / 120;           // both outputs concatenated in d_out
        has_edges = true;
    } else if (oo % (K_SEL * L_PATH) == 0 && np_sz == (oo / 64) * 256) {
        n_node_ll = oo / 64;            // only paths_sel fits in d_out
        has_edges = false;
    } else {
        n_node_ll = np_sz / (N_PATH * L_PATH);
        has_edges = (oo >= n_node_ll * 120);
    }

    int i_lens = -1, i_cent = -1;
    for (int i = 0; i < m; i++) {
        if (i == i_paths || i == i_edges) continue;
        if (sz[i] == n_node_ll * N_PATH) i_lens = i;
    }
    for (int i = 0; i < m; i++) {
        if (i == i_paths || i == i_edges || i == i_lens) continue;
        if (sz[i] > 4) i_cent = i;
    }
    if (i_lens < 0) i_lens = 2;
    if (i_cent < 0) i_cent = 3;

    const int*   paths      = (const int*)  ptr[i_paths];
    const int*   edge_ids   = (const int*)  ptr[i_edges];
    const int*   rand_lens  = (const int*)  ptr[i_lens];
    const float* centrality = (const float*)ptr[i_cent];
    const int    n_node     = (int)n_node_ll;

    float* out_paths = (float*)d_out;
    float* out_edges = has_edges ? out_paths + (size_t)n_node * K_SEL * L_PATH
                                 : nullptr;

    const int threads = 256;                 // 8 warps/block, 2 nodes/warp
    const long long warps_needed = (n_node_ll + 1) / 2;
    const int blocks = (int)((warps_needed * 32 + threads - 1) / threads);
    path_sampling_kernel<<<blocks, threads>>>(paths, edge_ids, rand_lens,
                                              centrality, out_paths,
                                              out_edges, n_node);
}